// round 2
// baseline (speedup 1.0000x reference)
#include <cuda_runtime.h>
#include <math.h>

// ---------------------------------------------------------------------------
// Problem constants
// ---------------------------------------------------------------------------
#define TSEQ  64
#define BATCH 512
#define EBD   256
#define VFD   512
#define SENSD 768          // EBD + VFD
#define H0    512
#define H1    256
#define H2    64
#define C0    1280         // SENSD + H0
#define C1    768          // H0 + H1
#define C2    320          // H1 + H2
#define N0    2048         // 4*H0 (interleaved ff1,ff2,ta,tb)
#define N1    1024
#define N2    256

// ---------------------------------------------------------------------------
// Device-global scratch (allocation-free rule: static __device__ arrays)
// ---------------------------------------------------------------------------
__device__ float g_W0x[SENSD * N0];   // layer0 input-part weights  [k][4j+q], premasked
__device__ float g_W0h[H0 * N0];      // layer0 recurrent-part weights
__device__ float g_W1 [C1 * N1];      // layer1 full weights
__device__ float g_W2 [C2 * N2];      // layer2 full weights
__device__ float g_b0 [N0];
__device__ float g_b1 [N1];
__device__ float g_b2 [N2];
__device__ float g_U0 [(size_t)TSEQ * BATCH * N0];  // precomputed sensory projections (256 MB)
__device__ float g_h0 [2 * BATCH * H0];             // double-buffered hidden states
__device__ float g_h1 [2 * BATCH * H1];
__device__ float g_h2 [2 * BATCH * H2];

// ---------------------------------------------------------------------------
// Weight prep: transpose to [k][n] with the 4 gate matrices interleaved per
// neuron (n = 4*j + q), mask applied to ff1/ff2 (mask is 1 on the recurrent
// block so applying it everywhere is exact).
// ---------------------------------------------------------------------------
__global__ void prep_weights(const float* __restrict__ ff1, const float* __restrict__ ff2,
                             const float* __restrict__ ta,  const float* __restrict__ tb,
                             const float* __restrict__ mask,
                             float* __restrict__ Wx, int Kx, float* __restrict__ Wh,
                             int C, int H)
{
    int idx = blockIdx.x * blockDim.x + threadIdx.x;
    int total = C * H;
    if (idx >= total) return;
    int k = idx / H;
    int j = idx - k * H;
    float mk = mask[j * C + k];
    float v0 = ff1[j * C + k] * mk;
    float v1 = ff2[j * C + k] * mk;
    float v2 = ta [j * C + k];
    float v3 = tb [j * C + k];
    float* dst = (k < Kx) ? (Wx + (size_t)k * (4 * H))
                          : (Wh + (size_t)(k - Kx) * (4 * H));
    int n = 4 * j;
    dst[n + 0] = v0; dst[n + 1] = v1; dst[n + 2] = v2; dst[n + 3] = v3;
}

__global__ void prep_bias(const float* __restrict__ b1, const float* __restrict__ b2,
                          const float* __restrict__ b3, const float* __restrict__ b4,
                          float* __restrict__ bo, int H)
{
    int j = blockIdx.x * blockDim.x + threadIdx.x;
    if (j >= H) return;
    bo[4 * j + 0] = b1[j];
    bo[4 * j + 1] = b2[j];
    bo[4 * j + 2] = b3[j];
    bo[4 * j + 3] = b4[j];
}

__global__ void zero_kernel(float* __restrict__ p, int n)
{
    int i = blockIdx.x * blockDim.x + threadIdx.x;
    if (i < n) p[i] = 0.f;
}

__global__ void copy_out(const float* __restrict__ src, float* __restrict__ dst, int n)
{
    int i = blockIdx.x * blockDim.x + threadIdx.x;
    if (i < n) dst[i] = src[i];
}

// ---------------------------------------------------------------------------
// Fused GEMM (+ optional CfC epilogue).
//   C[m][n] = sum_k X[m][k] * W[k][n]         (X = concat of xa (Ka cols), xb (Kb cols))
// SENSG: X rows are (t,b)-flattened and gathered from base/visual tensors.
// CFC:   n-quads (ff1,ff2,ta,tb) are combined into h_new and stored as [m][n/4].
// Tile: BM x BN, 256 threads, each computes TM x TN, BK = 16.
// ---------------------------------------------------------------------------
template<int BM, int BN, int TM, int TN, bool SENSG, bool CFC>
__global__ __launch_bounds__(256)
void cfc_gemm(const float* __restrict__ xa, int Ka,
              const float* __restrict__ xb, int Kb,
              const float* __restrict__ W,
              const float* __restrict__ bias,
              const float* __restrict__ uadd,
              float* __restrict__ out,
              int M, int N)
{
    constexpr int TX = BN / TN;
    constexpr int TY = BM / TM;
    static_assert(TX * TY == 256, "thread tiling mismatch");
    static_assert((TN % 4) == 0 || !CFC, "CFC needs neuron-aligned TN");

    __shared__ float Xs[BM][17];     // +1 pad to avoid bank conflicts
    __shared__ float Ws[16][BN];

    const int m0  = blockIdx.y * BM;
    const int n0  = blockIdx.x * BN;
    const int tid = threadIdx.x;
    const int tx  = tid % TX;
    const int ty  = tid / TX;

    float acc[TM][TN];
#pragma unroll
    for (int i = 0; i < TM; i++)
#pragma unroll
        for (int j = 0; j < TN; j++) acc[i][j] = 0.f;

    const int Kt = Ka + Kb;
    for (int k0 = 0; k0 < Kt; k0 += 16) {
        // --- load X tile (BM x 16) ---
#pragma unroll
        for (int i = tid; i < BM * 16; i += 256) {
            int mm = i >> 4, kk = i & 15;
            int kg = k0 + kk;
            int gm = m0 + mm;
            float v;
            if (SENSG) {
                int t = gm >> 9;          // gm / BATCH
                int b = gm & 511;         // gm % BATCH
                if (kg < Ka) v = xa[((size_t)b * TSEQ + t) * EBD + kg];
                else         v = xb[((size_t)b * TSEQ + t) * VFD + (kg - Ka)];
            } else {
                if (kg < Ka) v = xa[(size_t)gm * Ka + kg];
                else         v = xb[(size_t)gm * Kb + (kg - Ka)];
            }
            Xs[mm][kk] = v;
        }
        // --- load W tile (16 x BN) ---
#pragma unroll
        for (int i = tid; i < 16 * BN; i += 256) {
            int kk = i / BN, nn = i % BN;
            Ws[kk][nn] = W[(size_t)(k0 + kk) * N + (n0 + nn)];
        }
        __syncthreads();

#pragma unroll
        for (int kk = 0; kk < 16; kk++) {
            float xr[TM], wr[TN];
#pragma unroll
            for (int i = 0; i < TM; i++) xr[i] = Xs[ty * TM + i][kk];
#pragma unroll
            for (int j = 0; j < TN; j++) wr[j] = Ws[kk][tx * TN + j];
#pragma unroll
            for (int i = 0; i < TM; i++)
#pragma unroll
                for (int j = 0; j < TN; j++)
                    acc[i][j] += xr[i] * wr[j];
        }
        __syncthreads();
    }

    if (!CFC) {
#pragma unroll
        for (int i = 0; i < TM; i++) {
            int gm = m0 + ty * TM + i;
#pragma unroll
            for (int j = 0; j < TN; j++)
                out[(size_t)gm * N + (n0 + tx * TN + j)] = acc[i][j];
        }
    } else {
        const int Hd = N >> 2;
#pragma unroll
        for (int i = 0; i < TM; i++) {
            int gm = m0 + ty * TM + i;
#pragma unroll
            for (int g = 0; g < TN / 4; g++) {
                int n = n0 + tx * TN + g * 4;
                float f1v = acc[i][g * 4 + 0] + bias[n + 0];
                float f2v = acc[i][g * 4 + 1] + bias[n + 1];
                float tav = acc[i][g * 4 + 2] + bias[n + 2];
                float tbv = acc[i][g * 4 + 3] + bias[n + 3];
                if (uadd != nullptr) {
                    const float* u = uadd + (size_t)gm * N + n;
                    f1v += u[0]; f2v += u[1]; tav += u[2]; tbv += u[3];
                }
                float s = 1.f / (1.f + expf(-(tav + tbv)));
                float h = tanhf(f1v) * (1.f - s) + s * tanhf(f2v);
                out[(size_t)gm * Hd + (n >> 2)] = h;
            }
        }
    }
}

// ---------------------------------------------------------------------------
// kernel_launch
// ---------------------------------------------------------------------------
extern "C" void kernel_launch(void* const* d_in, const int* in_sizes, int n_in,
                              void* d_out, int out_size)
{
    (void)in_sizes; (void)n_in; (void)out_size;
    const float* base   = (const float*)d_in[0];
    const float* visual = (const float*)d_in[1];

    const float* w[3][4];   // ff1_w, ff2_w, ta_w, tb_w
    const float* bs[3][4];  // ff1_b, ff2_b, ta_b, tb_b
    const float* mk[3];
    for (int l = 0; l < 3; l++) {
        int o = 2 + l * 9;
        w[l][0]  = (const float*)d_in[o + 0];  bs[l][0] = (const float*)d_in[o + 1];
        w[l][1]  = (const float*)d_in[o + 2];  bs[l][1] = (const float*)d_in[o + 3];
        w[l][2]  = (const float*)d_in[o + 4];  bs[l][2] = (const float*)d_in[o + 5];
        w[l][3]  = (const float*)d_in[o + 6];  bs[l][3] = (const float*)d_in[o + 7];
        mk[l]    = (const float*)d_in[o + 8];
    }

    void* p;
    cudaGetSymbolAddress(&p, g_W0x); float* pW0x = (float*)p;
    cudaGetSymbolAddress(&p, g_W0h); float* pW0h = (float*)p;
    cudaGetSymbolAddress(&p, g_W1);  float* pW1  = (float*)p;
    cudaGetSymbolAddress(&p, g_W2);  float* pW2  = (float*)p;
    cudaGetSymbolAddress(&p, g_b0);  float* pb0  = (float*)p;
    cudaGetSymbolAddress(&p, g_b1);  float* pb1  = (float*)p;
    cudaGetSymbolAddress(&p, g_b2);  float* pb2  = (float*)p;
    cudaGetSymbolAddress(&p, g_U0);  float* pU0  = (float*)p;
    cudaGetSymbolAddress(&p, g_h0);  float* ph0  = (float*)p;
    cudaGetSymbolAddress(&p, g_h1);  float* ph1  = (float*)p;
    cudaGetSymbolAddress(&p, g_h2);  float* ph2  = (float*)p;

    // --- prep: masked/transposed/interleaved weights + interleaved biases ---
    prep_weights<<<(C0 * H0 + 255) / 256, 256>>>(w[0][0], w[0][1], w[0][2], w[0][3], mk[0],
                                                 pW0x, SENSD, pW0h, C0, H0);
    prep_weights<<<(C1 * H1 + 255) / 256, 256>>>(w[1][0], w[1][1], w[1][2], w[1][3], mk[1],
                                                 pW1, C1, pW1, C1, H1);
    prep_weights<<<(C2 * H2 + 255) / 256, 256>>>(w[2][0], w[2][1], w[2][2], w[2][3], mk[2],
                                                 pW2, C2, pW2, C2, H2);
    prep_bias<<<(H0 + 255) / 256, 256>>>(bs[0][0], bs[0][1], bs[0][2], bs[0][3], pb0, H0);
    prep_bias<<<(H1 + 255) / 256, 256>>>(bs[1][0], bs[1][1], bs[1][2], bs[1][3], pb1, H1);
    prep_bias<<<(H2 + 255) / 256, 256>>>(bs[2][0], bs[2][1], bs[2][2], bs[2][3], pb2, H2);

    // --- zero initial hidden states (buffer 0) ---
    zero_kernel<<<(BATCH * H0 + 255) / 256, 256>>>(ph0, BATCH * H0);
    zero_kernel<<<(BATCH * H1 + 255) / 256, 256>>>(ph1, BATCH * H1);
    zero_kernel<<<(BATCH * H2 + 255) / 256, 256>>>(ph2, BATCH * H2);

    // --- precompute layer-0 sensory projections for ALL timesteps (one big GEMM) ---
    // U0[t*B + b][n] = x_sens[t,b,:] @ W0x   (M = 32768, K = 768, N = 2048)
    cfc_gemm<64, 128, 4, 8, true, false>
        <<<dim3(N0 / 128, (TSEQ * BATCH) / 64), 256>>>(
            base, EBD, visual, VFD, pW0x, nullptr, nullptr, pU0, TSEQ * BATCH, N0);

    // --- sequential recurrence: 3 dependent fused GEMM+CfC kernels per step ---
    for (int t = 0; t < TSEQ; t++) {
        float* h0r = ph0 + (size_t)(t & 1) * BATCH * H0;
        float* h0w = ph0 + (size_t)((t + 1) & 1) * BATCH * H0;
        float* h1r = ph1 + (size_t)(t & 1) * BATCH * H1;
        float* h1w = ph1 + (size_t)((t + 1) & 1) * BATCH * H1;
        float* h2r = ph2 + (size_t)(t & 1) * BATCH * H2;
        float* h2w = ph2 + (size_t)((t + 1) & 1) * BATCH * H2;

        // layer 0: recurrent K=512 GEMM + precomputed U0 slice
        cfc_gemm<64, 128, 4, 8, false, true>
            <<<dim3(N0 / 128, BATCH / 64), 256>>>(
                h0r, H0, h0r, 0, pW0h, pb0,
                pU0 + (size_t)t * BATCH * N0, h0w, BATCH, N0);

        // layer 1: input = fresh h0, recurrent = h1   (K = 768)
        cfc_gemm<32, 128, 2, 8, false, true>
            <<<dim3(N1 / 128, BATCH / 32), 256>>>(
                h0w, H0, h1r, H1, pW1, pb1, nullptr, h1w, BATCH, N1);

        // layer 2: input = fresh h1, recurrent = h2   (K = 320)
        cfc_gemm<32, 64, 2, 4, false, true>
            <<<dim3(N2 / 64, BATCH / 32), 256>>>(
                h1w, H1, h2r, H2, pW2, pb2, nullptr, h2w, BATCH, N2);
    }

    // final motor state: t=63 wrote buffer (63+1)&1 = 0
    copy_out<<<(BATCH * H2 + 255) / 256, 256>>>(ph2, (float*)d_out, BATCH * H2);
}

// round 8
// speedup vs baseline: 3.4506x; 3.4506x over previous
#include <cuda_runtime.h>
#include <cuda_bf16.h>
#include <cstdint>
#include <math.h>

// ---------------------------------------------------------------------------
// Problem constants
// ---------------------------------------------------------------------------
#define TSEQ  64
#define BATCH 512
#define EBD   256
#define VFD   512
#define SENSD 768          // EBD + VFD
#define H0    512
#define H1    256
#define H2    64
#define C0    1280         // SENSD + H0
#define C1    768          // H0 + H1
#define C2    320          // H1 + H2
#define N0    2048         // 4*H0 (interleaved ff1,ff2,ta,tb, permuted)
#define N1    1024
#define N2    256

// ---------------------------------------------------------------------------
// Device-global scratch. Packed weights: per (nb, kc) block = 32 KB:
//   [hi 16KB: 128 n-rows x 64 k bf16, 128B rows, SW128-swizzled][lo 16KB same]
// Byte sizes identical to the fp32 originals.
// ---------------------------------------------------------------------------
__device__ float g_W0x[SENSD * N0];   // 16 nb x 12 kc
__device__ float g_W0h[H0 * N0];      // 16 nb x  8 kc
__device__ float g_W1 [C1 * N1];      //  8 nb x 12 kc
__device__ float g_W2 [C2 * N2];      //  2 nb x  5 kc
__device__ float g_b0 [N0];
__device__ float g_b1 [N1];
__device__ float g_b2 [N2];
__device__ float g_U0 [(size_t)TSEQ * BATCH * N0];  // precomputed sensory proj (physical layout)
__device__ float g_h0 [2 * BATCH * H0];             // double-buffered hidden states
__device__ float g_h1 [2 * BATCH * H1];
__device__ float g_h2 [2 * BATCH * H2];

// ---------------------------------------------------------------------------
// Helpers (portable PTX only: mma.sync / ldmatrix / cp.async — no tcgen05)
// ---------------------------------------------------------------------------
__device__ __forceinline__ uint32_t smem_u32(const void* p) {
    uint32_t a;
    asm("{ .reg .u64 t; cvta.to.shared.u64 t, %1; cvt.u32.u64 %0, t; }" : "=r"(a) : "l"(p));
    return a;
}
#define SWZ(o) ((o) ^ (((o) >> 3) & 0x70))

#define LDSM_X4(r0, r1, r2, r3, a) \
    asm volatile("ldmatrix.sync.aligned.m8n8.x4.shared.b16 {%0,%1,%2,%3}, [%4];" \
                 : "=r"(r0), "=r"(r1), "=r"(r2), "=r"(r3) : "r"(a))
#define LDSM_X2(r0, r1, a) \
    asm volatile("ldmatrix.sync.aligned.m8n8.x2.shared.b16 {%0,%1}, [%2];" \
                 : "=r"(r0), "=r"(r1) : "r"(a))

__device__ __forceinline__ void mma16816(float (&d)[4], const uint32_t (&a)[4],
                                         const uint32_t (&b)[2]) {
    asm volatile(
        "mma.sync.aligned.m16n8k16.row.col.f32.bf16.bf16.f32 "
        "{%0,%1,%2,%3}, {%4,%5,%6,%7}, {%8,%9}, {%0,%1,%2,%3};"
        : "+f"(d[0]), "+f"(d[1]), "+f"(d[2]), "+f"(d[3])
        : "r"(a[0]), "r"(a[1]), "r"(a[2]), "r"(a[3]), "r"(b[0]), "r"(b[1]));
}

#define CP_ASYNC16(dst, src) \
    asm volatile("cp.async.cg.shared.global [%0], [%1], 16;" :: "r"(dst), "l"(src))
#define CP_COMMIT() asm volatile("cp.async.commit_group;" ::: "memory")
#define CP_WAIT0()  asm volatile("cp.async.wait_group 0;" ::: "memory")

__device__ __forceinline__ uint32_t pack_bf2(__nv_bfloat16 a, __nv_bfloat16 b) {
    uint16_t ua = *(uint16_t*)&a, ub = *(uint16_t*)&b;
    return (uint32_t)ua | ((uint32_t)ub << 16);
}

// ---------------------------------------------------------------------------
// Column permutation: logical col n (= 4j+q, gate-interleaved) -> physical col.
// Within each 32-col group, quads land on single-thread MMA accumulator pairs:
//   Q = L/4, r = L%4 : permL = (Q%4)*2 + (r%2) + 8*((Q/4)*2 + r/2)
// ---------------------------------------------------------------------------
__host__ __device__ __forceinline__ int perm_col(int n) {
    int grp = n >> 5, L = n & 31, Q = L >> 2, r = L & 3;
    int pl = ((Q & 3) << 1) + (r & 1) + (((Q >> 2) << 1) + (r >> 1)) * 8;
    return (grp << 5) + pl;
}

// ---------------------------------------------------------------------------
// Weight prep: masked, hi/lo split, transposed to [n][k], gate-interleaved +
// permuted, scattered into the swizzled 32KB blocks (nb = 128 cols, kc = 64 k).
// ---------------------------------------------------------------------------
__global__ void prep_weights(const float* __restrict__ ff1, const float* __restrict__ ff2,
                             const float* __restrict__ ta,  const float* __restrict__ tb,
                             const float* __restrict__ mask,
                             float* __restrict__ Wx, int Kx, int KCx,
                             float* __restrict__ Wh, int KCh,
                             int C, int H)
{
    int idx = blockIdx.x * blockDim.x + threadIdx.x;
    if (idx >= C * H) return;
    int k = idx / H;
    int j = idx - k * H;
    float mk = mask[j * C + k];
    float v[4];
    v[0] = ff1[j * C + k] * mk;
    v[1] = ff2[j * C + k] * mk;
    v[2] = ta [j * C + k];
    v[3] = tb [j * C + k];

    char* base; int kc, KC;
    if (k < Kx) { base = (char*)Wx; kc = k >> 6;        KC = KCx; }
    else        { base = (char*)Wh; kc = (k - Kx) >> 6; KC = KCh; }
    int kr = (k < Kx ? k : k - Kx) & 63;

#pragma unroll
    for (int q = 0; q < 4; q++) {
        int P  = perm_col(4 * j + q);
        int nb = P >> 7, nr = P & 127;
        size_t blk = (size_t)(nb * KC + kc) * 32768;
        uint32_t off = SWZ((uint32_t)(nr * 128 + kr * 2));
        float x = v[q];
        __nv_bfloat16 h = __float2bfloat16(x);
        __nv_bfloat16 l = __float2bfloat16(x - __bfloat162float(h));
        *(__nv_bfloat16*)(base + blk + off)         = h;
        *(__nv_bfloat16*)(base + blk + 16384 + off) = l;
    }
}

__global__ void prep_bias(const float* __restrict__ b1, const float* __restrict__ b2,
                          const float* __restrict__ b3, const float* __restrict__ b4,
                          float* __restrict__ bo, int H)
{
    int j = blockIdx.x * blockDim.x + threadIdx.x;
    if (j >= H) return;
    bo[4 * j + 0] = b1[j];
    bo[4 * j + 1] = b2[j];
    bo[4 * j + 2] = b3[j];
    bo[4 * j + 3] = b4[j];
}

__global__ void zero_kernel(float* __restrict__ p, int n)
{
    int i = blockIdx.x * blockDim.x + threadIdx.x;
    if (i < n) p[i] = 0.f;
}

__global__ void copy_out(const float* __restrict__ src, float* __restrict__ dst, int n)
{
    int i = blockIdx.x * blockDim.x + threadIdx.x;
    if (i < n) dst[i] = src[i];
}

// ---------------------------------------------------------------------------
// Split-bf16 HMMA GEMM (+ optional fused CfC epilogue).
// CTA tile 64(M) x 128(N), 8 warps (2M x 4N), warp tile 32x32, K-chunks of 64,
// double-buffered SMEM, cp.async for pre-swizzled weight blocks.
// Stage layout: AH 8K | AL 8K | BH 16K | BL 16K = 48KB, x2 stages.
// ---------------------------------------------------------------------------
#define ST_AH 0
#define ST_AL 8192
#define ST_BH 16384
#define ST_BL 32768
#define ST_BYTES 49152
#define SMEM_BYTES (2 * ST_BYTES)   // 98304

template<bool SENSG>
__device__ __forceinline__ void load_a_regs(const float* __restrict__ xa, int Ka,
                                            const float* __restrict__ xb, int Kb,
                                            int m0, int k0, int tid, float* ar)
{
#pragma unroll
    for (int it = 0; it < 4; it++) {
        int idx = tid + it * 256;
        int row = idx >> 4, cg = idx & 15;
        int gm  = m0 + row;
        int kg  = k0 + cg * 4;
        const float* src;
        if (SENSG) {
            int t = gm >> 9, bb = gm & 511;
            if (kg < EBD) src = xa + (size_t)(bb * TSEQ + t) * EBD + kg;
            else          src = xb + (size_t)(bb * TSEQ + t) * VFD + (kg - EBD);
        } else {
            if (kg < Ka) src = xa + (size_t)gm * Ka + kg;
            else         src = xb + (size_t)gm * Kb + (kg - Ka);
        }
        float4 v = *(const float4*)src;
        ar[it * 4 + 0] = v.x; ar[it * 4 + 1] = v.y;
        ar[it * 4 + 2] = v.z; ar[it * 4 + 3] = v.w;
    }
}

template<bool SENSG, bool CFC>
__global__ __launch_bounds__(256, 2)
void cfc_mma(const float* __restrict__ xa, int Ka,
             const float* __restrict__ xb, int Kb,
             const float* __restrict__ Wp,
             const float* __restrict__ bias,
             const float* __restrict__ uadd,
             float* __restrict__ out,
             int N)
{
    extern __shared__ char smem[];
    const uint32_t smem_base = smem_u32(smem);

    const int tid  = threadIdx.x;
    const int wid  = tid >> 5;
    const int lane = tid & 31;
    const int wm   = wid >> 2;          // 0..1  (M warp)
    const int wn   = wid & 3;           // 0..3  (N warp)
    const int g    = lane >> 2;         // group 0..7
    const int tg   = lane & 3;

    const int m0  = blockIdx.y * 64;
    const int n0  = blockIdx.x * 128;
    const int Kt  = Ka + Kb;
    const int nch = Kt >> 6;

    float acc[2][4][4];
#pragma unroll
    for (int a = 0; a < 2; a++)
#pragma unroll
        for (int b = 0; b < 4; b++)
#pragma unroll
            for (int c = 0; c < 4; c++) acc[a][b][c] = 0.f;

    float ar[16];
    load_a_regs<SENSG>(xa, Ka, xb, Kb, m0, 0, tid, ar);

    // prologue: cp.async B chunk 0
    {
        const char* ws = (const char*)Wp + (size_t)(blockIdx.x * nch) * 32768;
        uint32_t dst = smem_base + ST_BH;
#pragma unroll
        for (int j = 0; j < 8; j++) {
            int i = tid + j * 256;
            CP_ASYNC16(dst + i * 16, ws + i * 16);
        }
        CP_COMMIT();
    }

    for (int ch = 0; ch < nch; ch++) {
        const int bsel = ch & 1;
        char* stage = smem + bsel * ST_BYTES;
        const uint32_t stage_u = smem_base + (uint32_t)bsel * ST_BYTES;

        // ---- store A (hi/lo split, swizzled) for this chunk ----
#pragma unroll
        for (int it = 0; it < 4; it++) {
            int idx = tid + it * 256;
            int row = idx >> 4, cg = idx & 15;
            float x0 = ar[it * 4 + 0], x1 = ar[it * 4 + 1];
            float x2 = ar[it * 4 + 2], x3 = ar[it * 4 + 3];
            __nv_bfloat16 h0 = __float2bfloat16(x0);
            __nv_bfloat16 h1 = __float2bfloat16(x1);
            __nv_bfloat16 h2 = __float2bfloat16(x2);
            __nv_bfloat16 h3 = __float2bfloat16(x3);
            __nv_bfloat16 l0 = __float2bfloat16(x0 - __bfloat162float(h0));
            __nv_bfloat16 l1 = __float2bfloat16(x1 - __bfloat162float(h1));
            __nv_bfloat16 l2 = __float2bfloat16(x2 - __bfloat162float(h2));
            __nv_bfloat16 l3 = __float2bfloat16(x3 - __bfloat162float(h3));
            uint32_t off = SWZ((uint32_t)(row * 128 + cg * 8));
            *(uint2*)(stage + ST_AH + off) = make_uint2(pack_bf2(h0, h1), pack_bf2(h2, h3));
            *(uint2*)(stage + ST_AL + off) = make_uint2(pack_bf2(l0, l1), pack_bf2(l2, l3));
        }

        CP_WAIT0();
        __syncthreads();

        // ---- prefetch next chunk (overlaps with MMA below) ----
        if (ch + 1 < nch) {
            const char* ws = (const char*)Wp + (size_t)(blockIdx.x * nch + ch + 1) * 32768;
            uint32_t dst = smem_base + (uint32_t)((ch + 1) & 1) * ST_BYTES + ST_BH;
#pragma unroll
            for (int j = 0; j < 8; j++) {
                int i = tid + j * 256;
                CP_ASYNC16(dst + i * 16, ws + i * 16);
            }
            CP_COMMIT();
            load_a_regs<SENSG>(xa, Ka, xb, Kb, m0, (ch + 1) << 6, tid, ar);
        }

        // ---- MMA over 4 k16 steps of this 64-chunk ----
        const uint32_t sAh = stage_u + ST_AH;
        const uint32_t sAl = stage_u + ST_AL;
        const uint32_t sBh = stage_u + ST_BH;
        const uint32_t sBl = stage_u + ST_BL;
#pragma unroll
        for (int ks = 0; ks < 4; ks++) {
            uint32_t ah[2][4], al[2][4], bh[4][2], bl[4][2];
#pragma unroll
            for (int mt = 0; mt < 2; mt++) {
                int arow = wm * 32 + mt * 16 + (lane & 15);
                uint32_t aoff = SWZ((uint32_t)(arow * 128 + (ks * 16 + (lane >> 4) * 8) * 2));
                LDSM_X4(ah[mt][0], ah[mt][1], ah[mt][2], ah[mt][3], sAh + aoff);
                LDSM_X4(al[mt][0], al[mt][1], al[mt][2], al[mt][3], sAl + aoff);
            }
#pragma unroll
            for (int nt = 0; nt < 4; nt++) {
                int brow = wn * 32 + nt * 8 + (lane & 7);
                uint32_t boff = SWZ((uint32_t)(brow * 128 + (ks * 16 + ((lane >> 3) & 1) * 8) * 2));
                LDSM_X2(bh[nt][0], bh[nt][1], sBh + boff);
                LDSM_X2(bl[nt][0], bl[nt][1], sBl + boff);
            }
#pragma unroll
            for (int mt = 0; mt < 2; mt++)
#pragma unroll
                for (int nt = 0; nt < 4; nt++) {
                    mma16816(acc[mt][nt], ah[mt], bh[nt]);
                    mma16816(acc[mt][nt], ah[mt], bl[nt]);
                    mma16816(acc[mt][nt], al[mt], bh[nt]);
                }
        }
        __syncthreads();
    }

    // ---- epilogue ----
    if (CFC) {
        const int Hd = N >> 2;
#pragma unroll
        for (int mt = 0; mt < 2; mt++) {
#pragma unroll
            for (int rh = 0; rh < 2; rh++) {
                int row = m0 + wm * 32 + mt * 16 + rh * 8 + g;
#pragma unroll
                for (int qi = 0; qi < 2; qi++) {
                    float f1  = acc[mt][2 * qi + 0][rh * 2 + 0];
                    float f2  = acc[mt][2 * qi + 0][rh * 2 + 1];
                    float tav = acc[mt][2 * qi + 1][rh * 2 + 0];
                    float tbv = acc[mt][2 * qi + 1][rh * 2 + 1];
                    int j = (n0 >> 2) + wn * 8 + qi * 4 + tg;
                    float4 bq = *(const float4*)(bias + 4 * j);
                    f1 += bq.x; f2 += bq.y; tav += bq.z; tbv += bq.w;
                    if (uadd != nullptr) {
                        int pc = n0 + wn * 32 + qi * 16 + tg * 2;
                        float2 u01 = *(const float2*)(uadd + (size_t)row * N + pc);
                        float2 u23 = *(const float2*)(uadd + (size_t)row * N + pc + 8);
                        f1 += u01.x; f2 += u01.y; tav += u23.x; tbv += u23.y;
                    }
                    float s = 1.f / (1.f + expf(-(tav + tbv)));
                    out[(size_t)row * Hd + j] = tanhf(f1) * (1.f - s) + s * tanhf(f2);
                }
            }
        }
    } else {
#pragma unroll
        for (int mt = 0; mt < 2; mt++)
#pragma unroll
            for (int rh = 0; rh < 2; rh++) {
                int row = m0 + wm * 32 + mt * 16 + rh * 8 + g;
#pragma unroll
                for (int nt = 0; nt < 4; nt++) {
                    int col = n0 + wn * 32 + nt * 8 + tg * 2;
                    float2 v = make_float2(acc[mt][nt][rh * 2 + 0], acc[mt][nt][rh * 2 + 1]);
                    *(float2*)(out + (size_t)row * N + col) = v;
                }
            }
    }
}

// ---------------------------------------------------------------------------
// kernel_launch
// ---------------------------------------------------------------------------
extern "C" void kernel_launch(void* const* d_in, const int* in_sizes, int n_in,
                              void* d_out, int out_size)
{
    (void)in_sizes; (void)n_in; (void)out_size;
    const float* base   = (const float*)d_in[0];
    const float* visual = (const float*)d_in[1];

    const float* w[3][4];
    const float* bs[3][4];
    const float* mk[3];
    for (int l = 0; l < 3; l++) {
        int o = 2 + l * 9;
        w[l][0] = (const float*)d_in[o + 0];  bs[l][0] = (const float*)d_in[o + 1];
        w[l][1] = (const float*)d_in[o + 2];  bs[l][1] = (const float*)d_in[o + 3];
        w[l][2] = (const float*)d_in[o + 4];  bs[l][2] = (const float*)d_in[o + 5];
        w[l][3] = (const float*)d_in[o + 6];  bs[l][3] = (const float*)d_in[o + 7];
        mk[l]   = (const float*)d_in[o + 8];
    }

    void* p;
    cudaGetSymbolAddress(&p, g_W0x); float* pW0x = (float*)p;
    cudaGetSymbolAddress(&p, g_W0h); float* pW0h = (float*)p;
    cudaGetSymbolAddress(&p, g_W1);  float* pW1  = (float*)p;
    cudaGetSymbolAddress(&p, g_W2);  float* pW2  = (float*)p;
    cudaGetSymbolAddress(&p, g_b0);  float* pb0  = (float*)p;
    cudaGetSymbolAddress(&p, g_b1);  float* pb1  = (float*)p;
    cudaGetSymbolAddress(&p, g_b2);  float* pb2  = (float*)p;
    cudaGetSymbolAddress(&p, g_U0);  float* pU0  = (float*)p;
    cudaGetSymbolAddress(&p, g_h0);  float* ph0  = (float*)p;
    cudaGetSymbolAddress(&p, g_h1);  float* ph1  = (float*)p;
    cudaGetSymbolAddress(&p, g_h2);  float* ph2  = (float*)p;

    cudaFuncSetAttribute(cfc_mma<true,  false>,
                         cudaFuncAttributeMaxDynamicSharedMemorySize, SMEM_BYTES);
    cudaFuncSetAttribute(cfc_mma<false, true>,
                         cudaFuncAttributeMaxDynamicSharedMemorySize, SMEM_BYTES);

    // --- prep: pack weights into swizzled bf16 hi/lo blocks, interleave biases ---
    prep_weights<<<(C0 * H0 + 255) / 256, 256>>>(w[0][0], w[0][1], w[0][2], w[0][3], mk[0],
                                                 pW0x, SENSD, 12, pW0h, 8, C0, H0);
    prep_weights<<<(C1 * H1 + 255) / 256, 256>>>(w[1][0], w[1][1], w[1][2], w[1][3], mk[1],
                                                 pW1, C1, 12, pW1, 1, C1, H1);
    prep_weights<<<(C2 * H2 + 255) / 256, 256>>>(w[2][0], w[2][1], w[2][2], w[2][3], mk[2],
                                                 pW2, C2, 5, pW2, 1, C2, H2);
    prep_bias<<<(H0 + 255) / 256, 256>>>(bs[0][0], bs[0][1], bs[0][2], bs[0][3], pb0, H0);
    prep_bias<<<(H1 + 255) / 256, 256>>>(bs[1][0], bs[1][1], bs[1][2], bs[1][3], pb1, H1);
    prep_bias<<<(H2 + 255) / 256, 256>>>(bs[2][0], bs[2][1], bs[2][2], bs[2][3], pb2, H2);

    // --- zero initial hidden states (buffer 0) ---
    zero_kernel<<<(BATCH * H0 + 255) / 256, 256>>>(ph0, BATCH * H0);
    zero_kernel<<<(BATCH * H1 + 255) / 256, 256>>>(ph1, BATCH * H1);
    zero_kernel<<<(BATCH * H2 + 255) / 256, 256>>>(ph2, BATCH * H2);

    // --- U0 = X_sens @ W0x for all timesteps (M=32768, K=768, N=2048) ---
    cfc_mma<true, false>
        <<<dim3(N0 / 128, (TSEQ * BATCH) / 64), 256, SMEM_BYTES>>>(
            base, EBD, visual, VFD, pW0x, nullptr, nullptr, pU0, N0);

    // --- sequential recurrence: 3 dependent fused GEMM+CfC kernels per step ---
    for (int t = 0; t < TSEQ; t++) {
        float* h0r = ph0 + (size_t)(t & 1) * BATCH * H0;
        float* h0w = ph0 + (size_t)((t + 1) & 1) * BATCH * H0;
        float* h1r = ph1 + (size_t)(t & 1) * BATCH * H1;
        float* h1w = ph1 + (size_t)((t + 1) & 1) * BATCH * H1;
        float* h2r = ph2 + (size_t)(t & 1) * BATCH * H2;
        float* h2w = ph2 + (size_t)((t + 1) & 1) * BATCH * H2;

        // layer 0: K=512 recurrent GEMM + precomputed U0 slice
        cfc_mma<false, true>
            <<<dim3(N0 / 128, BATCH / 64), 256, SMEM_BYTES>>>(
                h0r, H0, h0r, 0, pW0h, pb0,
                pU0 + (size_t)t * BATCH * N0, h0w, N0);

        // layer 1: input = fresh h0, recurrent = h1 (K=768)
        cfc_mma<false, true>
            <<<dim3(N1 / 128, BATCH / 64), 256, SMEM_BYTES>>>(
                h0w, H0, h1r, H1, pW1, pb1, nullptr, h1w, N1);

        // layer 2: input = fresh h1, recurrent = h2 (K=320)
        cfc_mma<false, true>
            <<<dim3(N2 / 128, BATCH / 64), 256, SMEM_BYTES>>>(
                h1w, H1, h2r, H2, pW2, pb2, nullptr, h2w, N2);
    }

    // final motor state: t=63 wrote buffer (63+1)&1 = 0
    copy_out<<<(BATCH * H2 + 255) / 256, 256>>>(ph2, (float*)d_out, BATCH * H2);
}